// round 4
// baseline (speedup 1.0000x reference)
#include <cuda_runtime.h>

#define NS 16
#define NZ 1000
#define NX 1000

#define DT_F    0.001f
#define HDT_F   0.0005f   // dt/2
#define INV_H_F 0.1f      // 1/h

#define TZ  8
#define TX  128           // tile width; block = 32x8, 4 elems/thread
#define SW  136           // staged smem row width (34 float4)
#define SPW 132           // sP row width (129 used)

#define AXW   (NX - 1)    // 999
#define AZW   (NX - 2)    // 998
#define AXROWS (NZ - 2)   // 998
#define AZROWS (NZ - 1)   // 999

__global__ __launch_bounds__(256)
void pml_step_kernel(
    const float* __restrict__ Px,   const float* __restrict__ Pz,
    const float* __restrict__ Ax,   const float* __restrict__ Az,
    const float* __restrict__ src,
    const float* __restrict__ m2dt,
    const float* __restrict__ sigx, const float* __restrict__ sxh,
    const float* __restrict__ sigz, const float* __restrict__ szh,
    float* __restrict__ oPx, float* __restrict__ oPz,
    float* __restrict__ oAx, float* __restrict__ oAz,
    float* __restrict__ oP)
{
    __shared__ float sAx[9][SW];    // Ax rows z0-1 .. z0+7
    __shared__ float sAz[10][SW];   // Az rows z0-1 .. z0+8
    __shared__ float sSx[8][SW];    // sxh rows z0-1 .. z0+6
    __shared__ float sSz[8][SW];    // szh rows z0   .. z0+7
    __shared__ float sP[TZ + 1][SPW];

    const int s  = blockIdx.z;
    const int z0 = blockIdx.y * TZ;
    const int x0 = blockIdx.x * TX;
    const int tx = threadIdx.x;     // 0..31
    const int ty = threadIdx.y;     // 0..7
    const int tid = ty * 32 + tx;

    const int sOffP  = s * (NZ * NX);
    const int sOffAx = s * (AXROWS * AXW);
    const int sOffAz = s * (AZROWS * AZW);

    // ---- Stage 0: cooperative aligned loads of all misaligned-row arrays ----
    // 35 row-segments x 34 float4 tasks = 1190 tasks.
    for (int t = tid; t < 35 * 34; t += 256) {
        const int row = t / 34;
        const int q   = t - row * 34;
        const float* gp; float* sr; int gBase, tot;
        bool valid, stream;
        if (row < 9) {
            const int gr = z0 - 1 + row;
            valid = (gr >= 0) && (gr < AXROWS);
            gp = Ax; sr = sAx[row]; gBase = sOffAx + gr * AXW;
            tot = NS * AXROWS * AXW; stream = true;
        } else if (row < 19) {
            const int r2 = row - 9, gr = z0 - 1 + r2;
            valid = (gr >= 0) && (gr < AZROWS);
            gp = Az; sr = sAz[r2]; gBase = sOffAz + gr * AZW;
            tot = NS * AZROWS * AZW; stream = true;
        } else if (row < 27) {
            const int r2 = row - 19, gr = z0 - 1 + r2;
            valid = (gr >= 0) && (gr < AXROWS);
            gp = sxh; sr = sSx[r2]; gBase = gr * AXW;
            tot = AXROWS * AXW; stream = false;
        } else {
            const int r2 = row - 27, gr = z0 + r2;
            valid = (gr < AZROWS);
            gp = szh; sr = sSz[r2]; gBase = gr * AZW;
            tot = AZROWS * AZW; stream = false;
        }
        if (!valid) continue;
        const int start = gBase + x0 - 1;          // >= -1
        const int f4 = (start >> 2) + q;           // float4 index of this task
        const int f0 = f4 * 4;
        if (f0 >= 0 && f0 + 3 < tot) {
            const float4 v = stream ? __ldcs((const float4*)(gp + f0))
                                    : *(const float4*)(gp + f0);
            *(float4*)(sr + q * 4) = v;
        } else {
            #pragma unroll
            for (int k = 0; k < 4; k++) {
                const int fi = f0 + k;
                sr[q * 4 + k] = (fi >= 0 && fi < tot) ? gp[fi] : 0.f;
            }
        }
    }
    __syncthreads();

    const int z = z0 + ty;
    const int x = x0 + 4 * tx;

    // ---- Phase 1: compute P on owned 8x128 tile (vectorized) ----
    if (x < NX) {
        const int g2 = z * NX + x;
        const int g3 = sOffP + g2;
        const float4 pxv = __ldcs((const float4*)(Px + g3));
        const float4 pzv = __ldcs((const float4*)(Pz + g3));
        const float4 srv = __ldcs((const float4*)(src + g3));
        const float4 mv  = *(const float4*)(m2dt + g2);
        const float4 sxv = *(const float4*)(sigx + g2);
        const float4 szv = *(const float4*)(sigz + g2);

        float axx[4] = {0.f, 0.f, 0.f, 0.f};
        float azz[4] = {0.f, 0.f, 0.f, 0.f};
        if (z >= 1 && z <= NZ - 2) {
            const int dAx  = (sOffAx + (z - 1) * AXW + x0 - 1) & 3;
            const int dAz0 = (sOffAz + (z - 1) * AZW + x0 - 1) & 3;
            const int dAz1 = (sOffAz +  z      * AZW + x0 - 1) & 3;
            const int b = 4 * tx;
            #pragma unroll
            for (int c = 0; c < 4; c++) {
                const int xi = x + c;
                if (xi >= 1 && xi <= NX - 2) {
                    axx[c] = (sAx[ty][dAx + b + c + 1] - sAx[ty][dAx + b + c]) * INV_H_F;
                    azz[c] = (sAz[ty + 1][dAz1 + b + c] - sAz[ty][dAz0 + b + c]) * INV_H_F;
                }
            }
        }

        const float px_in[4] = {pxv.x, pxv.y, pxv.z, pxv.w};
        const float pz_in[4] = {pzv.x, pzv.y, pzv.z, pzv.w};
        const float sr_in[4] = {srv.x, srv.y, srv.z, srv.w};
        const float m_in[4]  = {mv.x, mv.y, mv.z, mv.w};
        const float sx_in[4] = {sxv.x, sxv.y, sxv.z, sxv.w};
        const float sz_in[4] = {szv.x, szv.y, szv.z, szv.w};

        float pxn[4], pzn[4], pv[4];
        #pragma unroll
        for (int c = 0; c < 4; c++) {
            const float sx = sx_in[c] * HDT_F;
            const float sz = sz_in[c] * HDT_F;
            pxn[c] = __fdividef(fmaf(m_in[c], axx[c], (1.f - sx) * px_in[c]), 1.f + sx);
            pzn[c] = __fdividef(fmaf(m_in[c], azz[c], (1.f - sz) * pz_in[c]), 1.f + sz);
            pv[c]  = pxn[c] + pzn[c] + sr_in[c] * DT_F;
        }

        __stcs((float4*)(oPx + g3), make_float4(pxn[0], pxn[1], pxn[2], pxn[3]));
        __stcs((float4*)(oPz + g3), make_float4(pzn[0], pzn[1], pzn[2], pzn[3]));
        __stcs((float4*)(oP  + g3), make_float4(pv[0], pv[1], pv[2], pv[3]));
        *(float4*)&sP[ty][4 * tx] = make_float4(pv[0], pv[1], pv[2], pv[3]);
    }

    // ---- Halo P (smem-sourced derivatives, not stored to gmem) ----
    if (tid < TX) {                              // bottom row: z = z0+TZ
        const int hz = z0 + TZ;
        const int hx = x0 + tid;
        if (hz < NZ && hx < NX) {
            float ax_x = 0.f, az_z = 0.f;
            if (hz >= 1 && hz <= NZ - 2 && hx >= 1 && hx <= NX - 2) {
                const int dAx  = (sOffAx + (hz - 1) * AXW + x0 - 1) & 3;
                const int dAz0 = (sOffAz + (hz - 1) * AZW + x0 - 1) & 3;
                const int dAz1 = (sOffAz +  hz      * AZW + x0 - 1) & 3;
                ax_x = (sAx[8][dAx + tid + 1] - sAx[8][dAx + tid]) * INV_H_F;
                az_z = (sAz[9][dAz1 + tid] - sAz[8][dAz0 + tid]) * INV_H_F;
            }
            const int g2 = hz * NX + hx;
            const int g3 = sOffP + g2;
            const float sx = sigx[g2] * HDT_F;
            const float sz = sigz[g2] * HDT_F;
            const float m  = m2dt[g2];
            const float pxn = __fdividef(fmaf(m, ax_x, (1.f - sx) * __ldcs(Px + g3)), 1.f + sx);
            const float pzn = __fdividef(fmaf(m, az_z, (1.f - sz) * __ldcs(Pz + g3)), 1.f + sz);
            sP[TZ][tid] = pxn + pzn + __ldcs(src + g3) * DT_F;
        }
    } else if (tid < TX + TZ) {                  // right column: x = x0+TX
        const int r  = tid - TX;                 // 0..7
        const int hz = z0 + r;
        const int hx = x0 + TX;
        if (hx < NX) {
            float ax_x = 0.f, az_z = 0.f;
            if (hz >= 1 && hz <= NZ - 2 && hx <= NX - 2) {
                const int dAx  = (sOffAx + (hz - 1) * AXW + x0 - 1) & 3;
                const int dAz0 = (sOffAz + (hz - 1) * AZW + x0 - 1) & 3;
                const int dAz1 = (sOffAz +  hz      * AZW + x0 - 1) & 3;
                ax_x = (sAx[r][dAx + TX + 1] - sAx[r][dAx + TX]) * INV_H_F;
                az_z = (sAz[r + 1][dAz1 + TX] - sAz[r][dAz0 + TX]) * INV_H_F;
            }
            const int g2 = hz * NX + hx;
            const int g3 = sOffP + g2;
            const float sx = sigx[g2] * HDT_F;
            const float sz = sigz[g2] * HDT_F;
            const float m  = m2dt[g2];
            const float pxn = __fdividef(fmaf(m, ax_x, (1.f - sx) * __ldcs(Px + g3)), 1.f + sx);
            const float pzn = __fdividef(fmaf(m, az_z, (1.f - sz) * __ldcs(Pz + g3)), 1.f + sz);
            sP[r][TX] = pxn + pzn + __ldcs(src + g3) * DT_F;
        }
    }

    __syncthreads();

    if (x >= NX) return;

    // ---- Phase 2a: Ax_n at row i = z0+ty-1, cols x..x+3 ----
    {
        const int i = z0 + ty - 1;
        if (i >= 0 && i <= NZ - 3) {
            const float4 pvv = *(const float4*)&sP[ty][4 * tx];
            const float  pe  = sP[ty][4 * tx + 4];
            const float d[4] = {(pvv.y - pvv.x) * INV_H_F,
                                (pvv.z - pvv.y) * INV_H_F,
                                (pvv.w - pvv.z) * INV_H_F,
                                (pe    - pvv.w) * INV_H_F};
            const int dAx = (sOffAx + i * AXW + x0 - 1) & 3;
            const int dSx = (i * AXW + x0 - 1) & 3;
            const int base = sOffAx + i * AXW + x;
            const int b = 4 * tx;
            #pragma unroll
            for (int c = 0; c < 4; c++) {
                if (x + c <= NX - 2) {
                    const float sv   = sSx[ty][dSx + b + c + 1] * HDT_F;
                    const float aold = sAx[ty][dAx + b + c + 1];
                    __stcs(oAx + base + c,
                           __fdividef(fmaf(DT_F, d[c], (1.f - sv) * aold), 1.f + sv));
                }
            }
        }
    }

    // ---- Phase 2b: Az_n at row i = z0+ty, cols x-1..x+2 ----
    {
        const int i = z0 + ty;
        if (i <= NZ - 2) {
            const float4 pt = *(const float4*)&sP[ty][4 * tx];
            const float4 pb = *(const float4*)&sP[ty + 1][4 * tx];
            const float d[4] = {(pb.x - pt.x) * INV_H_F,
                                (pb.y - pt.y) * INV_H_F,
                                (pb.z - pt.z) * INV_H_F,
                                (pb.w - pt.w) * INV_H_F};
            const int dAz1 = (sOffAz + i * AZW + x0 - 1) & 3;
            const int dSz  = (i * AZW + x0 - 1) & 3;
            const int jb = x - 1;
            const int base = sOffAz + i * AZW + jb;
            const int b = 4 * tx;
            #pragma unroll
            for (int c = 0; c < 4; c++) {
                const int j = jb + c;
                if (j >= 0 && j <= NX - 3) {
                    const float sv   = sSz[ty][dSz + b + c] * HDT_F;
                    const float aold = sAz[ty + 1][dAz1 + b + c];
                    __stcs(oAz + base + c,
                           __fdividef(fmaf(DT_F, d[c], (1.f - sv) * aold), 1.f + sv));
                }
            }
        }
    }
}

extern "C" void kernel_launch(void* const* d_in, const int* in_sizes, int n_in,
                              void* d_out, int out_size)
{
    const float* Px   = (const float*)d_in[0];
    const float* Pz   = (const float*)d_in[1];
    const float* Ax   = (const float*)d_in[2];
    const float* Az   = (const float*)d_in[3];
    const float* src  = (const float*)d_in[4];
    const float* m2dt = (const float*)d_in[5];
    const float* sigx = (const float*)d_in[6];
    const float* sxh  = (const float*)d_in[7];
    const float* sigz = (const float*)d_in[8];
    const float* szh  = (const float*)d_in[9];

    float* out = (float*)d_out;
    const long long NP  = (long long)NS * NZ * NX;
    const long long NAX = (long long)NS * (NZ - 2) * (NX - 1);
    const long long NAZ = (long long)NS * (NZ - 1) * (NX - 2);

    float* oPx = out;
    float* oPz = oPx + NP;
    float* oAx = oPz + NP;
    float* oAz = oAx + NAX;
    float* oP  = oAz + NAZ;

    dim3 block(32, TZ, 1);
    dim3 grid((NX + TX - 1) / TX, (NZ + TZ - 1) / TZ, NS);

    pml_step_kernel<<<grid, block>>>(Px, Pz, Ax, Az, src,
                                     m2dt, sigx, sxh, sigz, szh,
                                     oPx, oPz, oAx, oAz, oP);
}